// round 13
// baseline (speedup 1.0000x reference)
#include <cuda_runtime.h>
#include <cuda_fp16.h>
#include <math.h>

#define DDIM 512
#define KCODES 1024
#define NR 65536
#define BM 128
#define BN 128
#define BK 64
#define NCH (DDIM/BK)        // 8
#define NSWEEP (KCODES/BN)   // 8
#define RSTR 144             // 128B row + 16 pad (conflict-free ldsm)
#define CAP 32
#define MARGIN 3.0e-3f
#define BMP 32               // phase2 rows per block

// dynamic smem layout (bytes)
#define OFF_CN   0
#define OFF_RMIN 4096
#define OFF_CNT  4608
#define OFF_LIST 5120
#define OFF_T    21504
#define TILEA    (BM*RSTR)           // 18432
#define TILEB    (BN*RSTR)           // 18432
#define BUF      (TILEA + TILEB)     // 36864: Ah, Bh
#define SMEM_TOTAL (OFF_T + 2*BUF)   // 95232 -> 2 CTAs/SM

__device__ float        g_cnorm[KCODES];
__device__ float        g_rnorm[NR];
__device__ unsigned int g_hist[KCODES];
__device__ double       g_sumsq;
__device__ __half       g_Ah[(size_t)NR * DDIM];
__device__ __half       g_Bh[KCODES * DDIM];
__device__ unsigned int g_candCnt[NR];
__device__ unsigned int g_cand[(size_t)NR * CAP];

// ---------------- helpers ----------------
__device__ __forceinline__ unsigned smem_u32(const void* p) {
    unsigned a;
    asm("{ .reg .u64 t; cvta.to.shared.u64 t, %1; cvt.u32.u64 %0, t; }" : "=r"(a) : "l"(p));
    return a;
}
// monotone float<->uint maps (unsigned order == float order, handles negatives)
__device__ __forceinline__ unsigned f2ord(float f) {
    unsigned b = __float_as_uint(f);
    return b ^ ((b & 0x80000000u) ? 0xFFFFFFFFu : 0x80000000u);
}
__device__ __forceinline__ float ord2f(unsigned k) {
    unsigned b = k ^ ((k & 0x80000000u) ? 0x80000000u : 0xFFFFFFFFu);
    return __uint_as_float(b);
}
__device__ __forceinline__ void ldsm4(unsigned* r, unsigned a) {
    asm volatile("ldmatrix.sync.aligned.m8n8.x4.shared.b16 {%0,%1,%2,%3}, [%4];"
        : "=r"(r[0]), "=r"(r[1]), "=r"(r[2]), "=r"(r[3]) : "r"(a));
}
__device__ __forceinline__ void mma16816(float* d, const unsigned* a, const unsigned* b) {
    asm volatile("mma.sync.aligned.m16n8k16.row.col.f32.f16.f16.f32 "
        "{%0,%1,%2,%3}, {%4,%5,%6,%7}, {%8,%9}, {%0,%1,%2,%3};"
        : "+f"(d[0]), "+f"(d[1]), "+f"(d[2]), "+f"(d[3])
        : "r"(a[0]), "r"(a[1]), "r"(a[2]), "r"(a[3]), "r"(b[0]), "r"(b[1]));
}
__device__ __forceinline__ void cpa16(unsigned dst, const void* src) {
    asm volatile("cp.async.cg.shared.global [%0], [%1], 16;" :: "r"(dst), "l"(src) : "memory");
}
#define CPA_COMMIT() asm volatile("cp.async.commit_group;" ::: "memory")
#define CPA_WAIT0()  asm volatile("cp.async.wait_group 0;" ::: "memory")

// ---------------- prep: codebook norms + f16 hi + zero accum ----------------
__global__ void vq_prep_cb(const float* __restrict__ cb) {
    int k = blockIdx.x, t = threadIdx.x;                    // 128 threads
    float4 q = ((const float4*)(cb + (size_t)k * DDIM))[t];
    double v = (double)__fmul_rn(q.x, q.x) + (double)__fmul_rn(q.y, q.y)
             + (double)__fmul_rn(q.z, q.z) + (double)__fmul_rn(q.w, q.w);
    #pragma unroll
    for (int o = 16; o; o >>= 1) v += __shfl_down_sync(0xFFFFFFFFu, v, o);
    __shared__ double ws[4];
    if ((t & 31) == 0) ws[t >> 5] = v;
    unsigned h0 = __half_as_ushort(__float2half_rn(q.x));
    unsigned h1 = __half_as_ushort(__float2half_rn(q.y));
    unsigned h2 = __half_as_ushort(__float2half_rn(q.z));
    unsigned h3 = __half_as_ushort(__float2half_rn(q.w));
    uint2 uh = {h0 | (h1 << 16), h2 | (h3 << 16)};
    ((uint2*)(g_Bh + (size_t)k * DDIM))[t] = uh;
    __syncthreads();
    if (t == 0) {
        g_cnorm[k] = (float)(ws[0] + ws[1] + ws[2] + ws[3]);
        g_hist[k] = 0u;
        if (k == 0) g_sumsq = 0.0;
    }
}

// ---------------- prep: per-row norms (f32 Kahan + f64 reduce) + A f16 hi ----------------
__global__ void vq_prep_rows(const float* __restrict__ in) {
    int wid = threadIdx.x >> 5, lid = threadIdx.x & 31;
    int row = blockIdx.x * 8 + wid;
    const float4* rp = (const float4*)(in + (size_t)row * DDIM);
    float s = 0.f, comp = 0.f;
    #pragma unroll
    for (int i = 0; i < 4; i++) {
        float4 v = rp[lid + i * 32];
        float sq[4] = {__fmul_rn(v.x, v.x), __fmul_rn(v.y, v.y),
                       __fmul_rn(v.z, v.z), __fmul_rn(v.w, v.w)};
        #pragma unroll
        for (int j = 0; j < 4; j++) {        // Kahan compensated sum (no FMA reassoc)
            float y = __fsub_rn(sq[j], comp);
            float t = __fadd_rn(s, y);
            comp = __fsub_rn(__fsub_rn(t, s), y);
            s = t;
        }
        unsigned h0 = __half_as_ushort(__float2half_rn(v.x));
        unsigned h1 = __half_as_ushort(__float2half_rn(v.y));
        unsigned h2 = __half_as_ushort(__float2half_rn(v.z));
        unsigned h3 = __half_as_ushort(__float2half_rn(v.w));
        uint2 uh = {h0 | (h1 << 16), h2 | (h3 << 16)};
        ((uint2*)(g_Ah + (size_t)row * DDIM))[lid + i * 32] = uh;
    }
    double d = (double)s - (double)comp;     // carry compensation into f64 reduce
    #pragma unroll
    for (int o = 16; o; o >>= 1) d += __shfl_down_sync(0xFFFFFFFFu, d, o);
    if (lid == 0) { g_rnorm[row] = (float)d; g_candCnt[row] = 0u; }
}

// ---------------- main: coarse f16 GEMM + margin candidate collection ----------------
__global__ void __launch_bounds__(256, 2)
vq_main(const float* __restrict__ in, const float* __restrict__ cb,
        float* __restrict__ out) {
    extern __shared__ char smem[];
    const unsigned sb = smem_u32(smem);
    float* cn_s = (float*)(smem + OFF_CN);
    unsigned* rowMinU = (unsigned*)(smem + OFF_RMIN);
    unsigned* cnt_s   = (unsigned*)(smem + OFF_CNT);
    unsigned* list_s  = (unsigned*)(smem + OFF_LIST);
    const int tid = threadIdx.x, l = tid & 31, wid = tid >> 5;
    const int wm = wid >> 2, wn = wid & 3;            // 2m x 4n warp grid
    const int rowBase = blockIdx.x * BM;

    for (int i = tid; i < KCODES; i += 256) cn_s[i] = g_cnorm[i];
    if (tid < BM) { rowMinU[tid] = 0xFFFFFFFFu; cnt_s[tid] = 0u; }

    const unsigned aRB  = (l & 15) * RSTR + (l >> 4) * 16;
    const unsigned bRB4 = ((l >> 4) * 8 + (l & 7)) * RSTR + ((l >> 3) & 1) * 16;
    // staging: row = tid>>1 (2 threads/row), 64B half = tid&1
    const int sRow = tid >> 1, sH = tid & 1;
    const unsigned sDst = sRow * RSTR + sH * 64;

    int rloc[8];
    #pragma unroll
    for (int s = 0; s < 8; s++)
        rloc[s] = wm * 64 + (s >> 1) * 16 + (s & 1) * 8 + (l >> 2);

    __syncthreads();

    for (int sw = 0; sw < NSWEEP; sw++) {
        const int kc0 = sw * BN;
        float D0[4][4][4];
        #pragma unroll
        for (int mt = 0; mt < 4; mt++)
            #pragma unroll
            for (int nt = 0; nt < 4; nt++)
                #pragma unroll
                for (int e = 0; e < 4; e++) D0[mt][nt][e] = 0.f;

        auto stage = [&](int c, int b) {
            const __half* pa = g_Ah + (size_t)(rowBase + sRow) * DDIM + c * BK + sH * 32;
            const __half* pb = g_Bh + (size_t)(kc0 + sRow) * DDIM + c * BK + sH * 32;
            const unsigned base = sb + OFF_T + b * BUF;
            cpa16(base + sDst,                pa);
            cpa16(base + sDst + 16,           pa + 8);
            cpa16(base + sDst + 32,           pa + 16);
            cpa16(base + sDst + 48,           pa + 24);
            cpa16(base + TILEA + sDst,        pb);
            cpa16(base + TILEA + sDst + 16,   pb + 8);
            cpa16(base + TILEA + sDst + 32,   pb + 16);
            cpa16(base + TILEA + sDst + 48,   pb + 24);
            CPA_COMMIT();
        };
        // 2-stage, 1 sync/chunk: wait0 -> sync -> stage(c+1) -> compute(c).
        // The sync publishes chunk c AND frees buf (c+1)&1 (last read compute(c-1)).
        stage(0, 0);
        for (int c = 0; c < NCH; c++) {
            CPA_WAIT0();
            __syncthreads();
            if (c + 1 < NCH) stage(c + 1, (c + 1) & 1);
            const unsigned base = sb + OFF_T + (c & 1) * BUF;
            #pragma unroll
            for (int kk = 0; kk < 4; kk++) {
                const unsigned ko = kk * 32;
                unsigned ah[4][4], bh[4][2];
                #pragma unroll
                for (int mt = 0; mt < 4; mt++)
                    ldsm4(ah[mt], base + (wm * 64 + mt * 16) * RSTR + aRB + ko);
                #pragma unroll
                for (int p = 0; p < 2; p++) {
                    unsigned t4[4];
                    ldsm4(t4, base + TILEA + (wn * 32 + p * 16) * RSTR + bRB4 + ko);
                    bh[2*p][0] = t4[0]; bh[2*p][1] = t4[1];
                    bh[2*p+1][0] = t4[2]; bh[2*p+1][1] = t4[3];
                }
                #pragma unroll
                for (int mt = 0; mt < 4; mt++)
                    #pragma unroll
                    for (int nt = 0; nt < 4; nt++)
                        mma16816(D0[mt][nt], ah[mt], bh[nt]);
            }
        }
        __syncthreads();   // last chunk's reads done before next sweep restages buf0

        // pass A: compute coarse scores in-place + running per-row min
        float sMin[8];
        #pragma unroll
        for (int s = 0; s < 8; s++) sMin[s] = 3.4e38f;
        #pragma unroll
        for (int mt = 0; mt < 4; mt++)
            #pragma unroll
            for (int nt = 0; nt < 4; nt++)
                #pragma unroll
                for (int e = 0; e < 4; e++) {
                    int col = kc0 + wn * 32 + nt * 8 + (l & 3) * 2 + (e & 1);
                    float s = __fsub_rn(cn_s[col], __fadd_rn(D0[mt][nt][e], D0[mt][nt][e]));
                    D0[mt][nt][e] = s;          // reuse in pass B
                    int slot = mt * 2 + (e >> 1);
                    if (s < sMin[slot]) sMin[slot] = s;
                }
        #pragma unroll
        for (int s = 0; s < 8; s++) {
            sMin[s] = fminf(sMin[s], __shfl_xor_sync(0xFFFFFFFFu, sMin[s], 1));
            sMin[s] = fminf(sMin[s], __shfl_xor_sync(0xFFFFFFFFu, sMin[s], 2));
        }
        if ((l & 3) == 0) {
            #pragma unroll
            for (int s = 0; s < 8; s++)
                atomicMin(&rowMinU[rloc[s]], f2ord(sMin[s]));
        }
        __syncthreads();
        // pass B: collect candidates within MARGIN of running row min
        float th[8];
        #pragma unroll
        for (int s = 0; s < 8; s++)
            th[s] = __fadd_rn(ord2f(rowMinU[rloc[s]]), MARGIN);
        #pragma unroll
        for (int mt = 0; mt < 4; mt++)
            #pragma unroll
            for (int nt = 0; nt < 4; nt++)
                #pragma unroll
                for (int e = 0; e < 4; e++) {
                    int slot = mt * 2 + (e >> 1);
                    if (D0[mt][nt][e] < th[slot]) {
                        int col = kc0 + wn * 32 + nt * 8 + (l & 3) * 2 + (e & 1);
                        unsigned pos = atomicAdd(&cnt_s[rloc[slot]], 1u);
                        if (pos < CAP) list_s[rloc[slot] * CAP + pos] = (unsigned)col;
                    }
                }
    }

    __syncthreads();
    if (tid < BM) g_candCnt[rowBase + tid] = cnt_s[tid];
    for (int i = tid; i < BM * CAP; i += 256) {
        int r = i / CAP, j = i % CAP;
        g_cand[(size_t)(rowBase + r) * CAP + j] = list_s[r * CAP + j];
    }
}

// ---------------- phase 2: exact rescoring (32 rows/block) + outputs ----------------
__global__ void __launch_bounds__(256)
vq_phase2(const float* __restrict__ in, const float* __restrict__ cb,
          float* __restrict__ out) {
    __shared__ unsigned cnts[BMP];
    __shared__ unsigned offs[BMP + 1];
    __shared__ unsigned char  pRow[BMP * CAP];
    __shared__ unsigned short pCand[BMP * CAP];
    __shared__ unsigned long long best[BMP];
    __shared__ int idx_s[BMP];
    __shared__ float red8[8];
    const int tid = threadIdx.x, l = tid & 31, wid = tid >> 5;
    const int rowBase = blockIdx.x * BMP;

    if (tid < BMP) {
        best[tid] = ~0ull;
        cnts[tid] = g_candCnt[rowBase + tid];
    }
    __syncthreads();
    if (tid == 0) {
        unsigned acc = 0;
        for (int r = 0; r < BMP; r++) {
            offs[r] = acc;
            unsigned c = cnts[r];
            acc += (c <= CAP) ? c : 0u;
        }
        offs[BMP] = acc;
    }
    __syncthreads();
    if (tid < BMP && cnts[tid] <= CAP) {
        unsigned o = offs[tid];
        for (unsigned j = 0; j < cnts[tid]; j++) {
            pRow[o + j] = (unsigned char)tid;
            pCand[o + j] = (unsigned short)g_cand[(size_t)(rowBase + tid) * CAP + j];
        }
    }
    __syncthreads();
    const unsigned total = offs[BMP];

    // warp-per-candidate: coalesced strided loads + deterministic tree-reduce
    for (unsigned i = wid; i < total; i += 8) {
        int r = pRow[i];
        int cand = pCand[i];
        const float* x = in + (size_t)(rowBase + r) * DDIM;
        const float* c = cb + (size_t)cand * DDIM;
        float acc = 0.f;
        #pragma unroll
        for (int k = 0; k < 16; k++)
            acc = __fmaf_rn(x[l + k * 32], c[l + k * 32], acc);
        #pragma unroll
        for (int o = 16; o; o >>= 1) acc += __shfl_xor_sync(0xFFFFFFFFu, acc, o);
        if (l == 0) {
            float s = __fsub_rn(__fadd_rn(g_rnorm[rowBase + r], g_cnorm[cand]),
                                __fmul_rn(2.0f, acc));
            unsigned long long key =
                ((unsigned long long)__float_as_uint(s) << 32) | (unsigned)cand;
            atomicMin(&best[r], key);
        }
    }
    // overflow fallback (expected never): warp-parallel full row scan
    for (int r = 0; r < BMP; r++) {
        if (cnts[r] > CAP) {
            const float* x = in + (size_t)(rowBase + r) * DDIM;
            for (int cand = wid; cand < KCODES; cand += 8) {
                const float* c = cb + (size_t)cand * DDIM;
                float acc = 0.f;
                #pragma unroll
                for (int k = 0; k < 16; k++)
                    acc = __fmaf_rn(x[l + k * 32], c[l + k * 32], acc);
                #pragma unroll
                for (int o = 16; o; o >>= 1) acc += __shfl_xor_sync(0xFFFFFFFFu, acc, o);
                if (l == 0) {
                    float s = __fsub_rn(__fadd_rn(g_rnorm[rowBase + r], g_cnorm[cand]),
                                        __fmul_rn(2.0f, acc));
                    unsigned long long key =
                        ((unsigned long long)__float_as_uint(s) << 32) | (unsigned)cand;
                    atomicMin(&best[r], key);
                }
            }
        }
    }
    __syncthreads();

    float lv = 0.f;
    if (tid < BMP) {
        unsigned long long k = best[tid];
        int bi = (int)(unsigned)(k & 0xFFFFFFFFull);
        float bs = __uint_as_float((unsigned)(k >> 32));
        idx_s[tid] = bi;
        atomicAdd(&g_hist[bi], 1u);
        lv = bs;                                // exact min lattice score = ||x-c||^2
    }
    #pragma unroll
    for (int o = 16; o; o >>= 1) lv += __shfl_down_sync(0xFFFFFFFFu, lv, o);
    if ((tid & 31) == 0) red8[wid] = lv;
    __syncthreads();
    if (tid == 0) {
        float s = 0.f;
        #pragma unroll
        for (int w = 0; w < 8; w++) s += red8[w];
        atomicAdd(&g_sumsq, (double)s);
    }
    // gather-write quantized
    for (int e = tid; e < BMP * DDIM; e += 256) {
        int rr = e >> 9, cc = e & 511;
        out[1 + (size_t)(rowBase + rr) * DDIM + cc] = cb[(size_t)idx_s[rr] * DDIM + cc];
    }
}

// ---------------- finalize scalars ----------------
__global__ void vq_final(float* __restrict__ out, int out_size) {
    int t = threadIdx.x;                            // 1024
    float p = (float)g_hist[t] / (float)NR;
    double term = (double)(p * logf(p + 1e-10f));
    #pragma unroll
    for (int o = 16; o; o >>= 1) term += __shfl_down_sync(0xFFFFFFFFu, term, o);
    __shared__ double ws[32];
    if ((t & 31) == 0) ws[t >> 5] = term;
    __syncthreads();
    if (t == 0) {
        double s = 0.0;
        #pragma unroll
        for (int w = 0; w < 32; w++) s += ws[w];
        double mean = g_sumsq / ((double)NR * (double)DDIM);
        out[0] = (float)(1.25 * mean);
        out[out_size - 1] = (float)exp(-s);
    }
}

extern "C" void kernel_launch(void* const* d_in, const int* in_sizes, int n_in,
                              void* d_out, int out_size) {
    const float* inputs = (const float*)d_in[0];
    const float* cb     = (const float*)d_in[1];
    float* out = (float*)d_out;
    int nrows = in_sizes[0] / DDIM;

    cudaFuncSetAttribute(vq_main, cudaFuncAttributeMaxDynamicSharedMemorySize, SMEM_TOTAL);
    vq_prep_cb<<<KCODES, 128>>>(cb);
    vq_prep_rows<<<nrows / 8, 256>>>(inputs);
    vq_main<<<nrows / BM, 256, SMEM_TOTAL>>>(inputs, cb, out);
    vq_phase2<<<nrows / BMP, 256>>>(inputs, cb, out);   // slot #4 for ncu
    vq_final<<<1, KCODES>>>(out, out_size);
}

// round 14
// speedup vs baseline: 1.0109x; 1.0109x over previous
#include <cuda_runtime.h>
#include <cuda_fp16.h>
#include <math.h>

#define DDIM 512
#define KCODES 1024
#define NR 65536
#define BM 128
#define BN 128
#define BK 32
#define NCH (DDIM/BK)        // 16
#define NSWEEP (KCODES/BN)   // 8
#define RSTR 80              // smem row stride bytes (conflict-free for ldsm)
#define CAP 32
#define MARGIN 3.0e-3f
#define BMP 64               // phase2 rows per block
#define P2T 512              // phase2 threads

// dynamic smem layout (bytes)
#define OFF_CN   0
#define OFF_RMIN 4096
#define OFF_CNT  4608
#define OFF_LIST 5120
#define OFF_T    21504
#define TILEA    (BM*RSTR)           // 10240
#define TILEB    (BN*RSTR)           // 10240
#define BUF      (TILEA + TILEB)     // 20480: Ah, Bh
#define SMEM_TOTAL (OFF_T + 4*BUF)   // 103424 -> 2 CTAs/SM

__device__ float        g_cnorm[KCODES];
__device__ float        g_rnorm[NR];
__device__ unsigned int g_hist[KCODES];
__device__ double       g_sumsq;
__device__ __half       g_Ah[(size_t)NR * DDIM];
__device__ __half       g_Bh[KCODES * DDIM];
__device__ unsigned int g_candCnt[NR];
__device__ unsigned int g_cand[(size_t)NR * CAP];

// ---------------- helpers ----------------
__device__ __forceinline__ unsigned smem_u32(const void* p) {
    unsigned a;
    asm("{ .reg .u64 t; cvta.to.shared.u64 t, %1; cvt.u32.u64 %0, t; }" : "=r"(a) : "l"(p));
    return a;
}
// monotone float<->uint maps (unsigned order == float order, handles negatives)
__device__ __forceinline__ unsigned f2ord(float f) {
    unsigned b = __float_as_uint(f);
    return b ^ ((b & 0x80000000u) ? 0xFFFFFFFFu : 0x80000000u);
}
__device__ __forceinline__ float ord2f(unsigned k) {
    unsigned b = k ^ ((k & 0x80000000u) ? 0x80000000u : 0xFFFFFFFFu);
    return __uint_as_float(b);
}
__device__ __forceinline__ void ldsm4(unsigned* r, unsigned a) {
    asm volatile("ldmatrix.sync.aligned.m8n8.x4.shared.b16 {%0,%1,%2,%3}, [%4];"
        : "=r"(r[0]), "=r"(r[1]), "=r"(r[2]), "=r"(r[3]) : "r"(a));
}
__device__ __forceinline__ void mma16816(float* d, const unsigned* a, const unsigned* b) {
    asm volatile("mma.sync.aligned.m16n8k16.row.col.f32.f16.f16.f32 "
        "{%0,%1,%2,%3}, {%4,%5,%6,%7}, {%8,%9}, {%0,%1,%2,%3};"
        : "+f"(d[0]), "+f"(d[1]), "+f"(d[2]), "+f"(d[3])
        : "r"(a[0]), "r"(a[1]), "r"(a[2]), "r"(a[3]), "r"(b[0]), "r"(b[1]));
}
__device__ __forceinline__ void cpa16(unsigned dst, const void* src) {
    asm volatile("cp.async.cg.shared.global [%0], [%1], 16;" :: "r"(dst), "l"(src) : "memory");
}
#define CPA_COMMIT() asm volatile("cp.async.commit_group;" ::: "memory")
#define CPA_WAIT2()  asm volatile("cp.async.wait_group 2;" ::: "memory")
#define CPA_WAIT1()  asm volatile("cp.async.wait_group 1;" ::: "memory")
#define CPA_WAIT0()  asm volatile("cp.async.wait_group 0;" ::: "memory")

// ---------------- prep: codebook norms + f16 hi + zero accum ----------------
__global__ void vq_prep_cb(const float* __restrict__ cb) {
    int k = blockIdx.x, t = threadIdx.x;                    // 128 threads
    float4 q = ((const float4*)(cb + (size_t)k * DDIM))[t];
    double v = (double)__fmul_rn(q.x, q.x) + (double)__fmul_rn(q.y, q.y)
             + (double)__fmul_rn(q.z, q.z) + (double)__fmul_rn(q.w, q.w);
    #pragma unroll
    for (int o = 16; o; o >>= 1) v += __shfl_down_sync(0xFFFFFFFFu, v, o);
    __shared__ double ws[4];
    if ((t & 31) == 0) ws[t >> 5] = v;
    unsigned h0 = __half_as_ushort(__float2half_rn(q.x));
    unsigned h1 = __half_as_ushort(__float2half_rn(q.y));
    unsigned h2 = __half_as_ushort(__float2half_rn(q.z));
    unsigned h3 = __half_as_ushort(__float2half_rn(q.w));
    uint2 uh = {h0 | (h1 << 16), h2 | (h3 << 16)};
    ((uint2*)(g_Bh + (size_t)k * DDIM))[t] = uh;
    __syncthreads();
    if (t == 0) {
        g_cnorm[k] = (float)(ws[0] + ws[1] + ws[2] + ws[3]);
        g_hist[k] = 0u;
        if (k == 0) g_sumsq = 0.0;
    }
}

// ---------------- prep: per-row norms (f32 Kahan + f64 reduce) + A f16 hi ----------------
__global__ void vq_prep_rows(const float* __restrict__ in) {
    int wid = threadIdx.x >> 5, lid = threadIdx.x & 31;
    int row = blockIdx.x * 8 + wid;
    const float4* rp = (const float4*)(in + (size_t)row * DDIM);
    float s = 0.f, comp = 0.f;
    #pragma unroll
    for (int i = 0; i < 4; i++) {
        float4 v = rp[lid + i * 32];
        float sq[4] = {__fmul_rn(v.x, v.x), __fmul_rn(v.y, v.y),
                       __fmul_rn(v.z, v.z), __fmul_rn(v.w, v.w)};
        #pragma unroll
        for (int j = 0; j < 4; j++) {        // Kahan compensated sum (no FMA reassoc)
            float y = __fsub_rn(sq[j], comp);
            float t = __fadd_rn(s, y);
            comp = __fsub_rn(__fsub_rn(t, s), y);
            s = t;
        }
        unsigned h0 = __half_as_ushort(__float2half_rn(v.x));
        unsigned h1 = __half_as_ushort(__float2half_rn(v.y));
        unsigned h2 = __half_as_ushort(__float2half_rn(v.z));
        unsigned h3 = __half_as_ushort(__float2half_rn(v.w));
        uint2 uh = {h0 | (h1 << 16), h2 | (h3 << 16)};
        ((uint2*)(g_Ah + (size_t)row * DDIM))[lid + i * 32] = uh;
    }
    double d = (double)s - (double)comp;     // carry compensation into f64 reduce
    #pragma unroll
    for (int o = 16; o; o >>= 1) d += __shfl_down_sync(0xFFFFFFFFu, d, o);
    if (lid == 0) { g_rnorm[row] = (float)d; g_candCnt[row] = 0u; }
}

// ---------------- main: coarse f16 GEMM + margin candidate collection ----------------
__global__ void __launch_bounds__(256, 2)
vq_main(const float* __restrict__ in, const float* __restrict__ cb,
        float* __restrict__ out) {
    extern __shared__ char smem[];
    const unsigned sb = smem_u32(smem);
    float* cn_s = (float*)(smem + OFF_CN);
    unsigned* rowMinU = (unsigned*)(smem + OFF_RMIN);
    unsigned* cnt_s   = (unsigned*)(smem + OFF_CNT);
    unsigned* list_s  = (unsigned*)(smem + OFF_LIST);
    const int tid = threadIdx.x, l = tid & 31, wid = tid >> 5;
    const int wm = wid >> 2, wn = wid & 3;            // 2m x 4n warp grid
    const int rowBase = blockIdx.x * BM;

    for (int i = tid; i < KCODES; i += 256) cn_s[i] = g_cnorm[i];
    if (tid < BM) { rowMinU[tid] = 0xFFFFFFFFu; cnt_s[tid] = 0u; }

    const unsigned aRB  = (l & 15) * RSTR + (l >> 4) * 16;
    const unsigned bRB4 = ((l >> 4) * 8 + (l & 7)) * RSTR + ((l >> 3) & 1) * 16;
    const int sRow = tid >> 1, sH = tid & 1;
    const unsigned sDst = sRow * RSTR + sH * 32;

    int rloc[8];
    #pragma unroll
    for (int s = 0; s < 8; s++)
        rloc[s] = wm * 64 + (s >> 1) * 16 + (s & 1) * 8 + (l >> 2);

    __syncthreads();

    for (int sw = 0; sw < NSWEEP; sw++) {
        const int kc0 = sw * BN;
        float D0[4][4][4];
        #pragma unroll
        for (int mt = 0; mt < 4; mt++)
            #pragma unroll
            for (int nt = 0; nt < 4; nt++)
                #pragma unroll
                for (int e = 0; e < 4; e++) D0[mt][nt][e] = 0.f;

        auto stage = [&](int c, int b) {
            const __half* pa = g_Ah + (size_t)(rowBase + sRow) * DDIM + c * BK + sH * 16;
            const __half* pb = g_Bh + (size_t)(kc0 + sRow) * DDIM + c * BK + sH * 16;
            const unsigned base = sb + OFF_T + b * BUF;
            cpa16(base + sDst,                pa);
            cpa16(base + sDst + 16,           pa + 8);
            cpa16(base + TILEA + sDst,        pb);
            cpa16(base + TILEA + sDst + 16,   pb + 8);
            CPA_COMMIT();
        };
        __syncthreads();                        // prior readers of all bufs done
        stage(0, 0);
        stage(1, 1);
        stage(2, 2);

        for (int c = 0; c < NCH; c++) {
            if (c < NCH - 2)       { CPA_WAIT2(); }
            else if (c == NCH - 2) { CPA_WAIT1(); }
            else                   { CPA_WAIT0(); }
            __syncthreads();                    // chunk c visible; compute(c-1) done
            if (c + 3 < NCH) stage(c + 3, (c + 3) & 3);
            const unsigned base = sb + OFF_T + (c & 3) * BUF;
            #pragma unroll
            for (int kk = 0; kk < 2; kk++) {
                const unsigned ko = kk * 32;
                unsigned ah[4][4], bh[4][2];
                #pragma unroll
                for (int mt = 0; mt < 4; mt++)
                    ldsm4(ah[mt], base + (wm * 64 + mt * 16) * RSTR + aRB + ko);
                #pragma unroll
                for (int p = 0; p < 2; p++) {
                    unsigned t4[4];
                    ldsm4(t4, base + TILEA + (wn * 32 + p * 16) * RSTR + bRB4 + ko);
                    bh[2*p][0] = t4[0]; bh[2*p][1] = t4[1];
                    bh[2*p+1][0] = t4[2]; bh[2*p+1][1] = t4[3];
                }
                #pragma unroll
                for (int mt = 0; mt < 4; mt++)
                    #pragma unroll
                    for (int nt = 0; nt < 4; nt++)
                        mma16816(D0[mt][nt], ah[mt], bh[nt]);
            }
        }

        // pass A: compute coarse scores in-place + running per-row min
        float sMin[8];
        #pragma unroll
        for (int s = 0; s < 8; s++) sMin[s] = 3.4e38f;
        #pragma unroll
        for (int mt = 0; mt < 4; mt++)
            #pragma unroll
            for (int nt = 0; nt < 4; nt++)
                #pragma unroll
                for (int e = 0; e < 4; e++) {
                    int col = kc0 + wn * 32 + nt * 8 + (l & 3) * 2 + (e & 1);
                    float s = __fsub_rn(cn_s[col], __fadd_rn(D0[mt][nt][e], D0[mt][nt][e]));
                    D0[mt][nt][e] = s;          // reuse in pass B
                    int slot = mt * 2 + (e >> 1);
                    if (s < sMin[slot]) sMin[slot] = s;
                }
        #pragma unroll
        for (int s = 0; s < 8; s++) {
            sMin[s] = fminf(sMin[s], __shfl_xor_sync(0xFFFFFFFFu, sMin[s], 1));
            sMin[s] = fminf(sMin[s], __shfl_xor_sync(0xFFFFFFFFu, sMin[s], 2));
        }
        if ((l & 3) == 0) {
            #pragma unroll
            for (int s = 0; s < 8; s++)
                atomicMin(&rowMinU[rloc[s]], f2ord(sMin[s]));
        }
        __syncthreads();
        // pass B: collect candidates within MARGIN of running row min
        float th[8];
        #pragma unroll
        for (int s = 0; s < 8; s++)
            th[s] = __fadd_rn(ord2f(rowMinU[rloc[s]]), MARGIN);
        #pragma unroll
        for (int mt = 0; mt < 4; mt++)
            #pragma unroll
            for (int nt = 0; nt < 4; nt++)
                #pragma unroll
                for (int e = 0; e < 4; e++) {
                    int slot = mt * 2 + (e >> 1);
                    if (D0[mt][nt][e] < th[slot]) {
                        int col = kc0 + wn * 32 + nt * 8 + (l & 3) * 2 + (e & 1);
                        unsigned pos = atomicAdd(&cnt_s[rloc[slot]], 1u);
                        if (pos < CAP) list_s[rloc[slot] * CAP + pos] = (unsigned)col;
                    }
                }
    }

    __syncthreads();
    if (tid < BM) g_candCnt[rowBase + tid] = cnt_s[tid];
    for (int i = tid; i < BM * CAP; i += 256) {
        int r = i / CAP, j = i % CAP;
        g_cand[(size_t)(rowBase + r) * CAP + j] = list_s[r * CAP + j];
    }
}

// ---------------- phase 2: exact rescoring (64 rows/block, 512 thr) + outputs ----------------
__global__ void __launch_bounds__(P2T)
vq_phase2(const float* __restrict__ in, const float* __restrict__ cb,
          float* __restrict__ out) {
    __shared__ unsigned cnts[BMP];
    __shared__ unsigned offs[BMP + 1];
    __shared__ unsigned char  pRow[BMP * CAP];
    __shared__ unsigned short pCand[BMP * CAP];
    __shared__ unsigned long long best[BMP];
    __shared__ int idx_s[BMP];
    __shared__ float red16[16];
    const int tid = threadIdx.x, l = tid & 31, wid = tid >> 5;
    const int rowBase = blockIdx.x * BMP;

    if (tid < BMP) {
        best[tid] = ~0ull;
        cnts[tid] = g_candCnt[rowBase + tid];
    }
    __syncthreads();
    if (tid == 0) {
        unsigned acc = 0;
        for (int r = 0; r < BMP; r++) {
            offs[r] = acc;
            unsigned c = cnts[r];
            acc += (c <= CAP) ? c : 0u;
        }
        offs[BMP] = acc;
    }
    __syncthreads();
    if (tid < BMP && cnts[tid] <= CAP) {
        unsigned o = offs[tid];
        for (unsigned j = 0; j < cnts[tid]; j++) {
            pRow[o + j] = (unsigned char)tid;
            pCand[o + j] = (unsigned short)g_cand[(size_t)(rowBase + tid) * CAP + j];
        }
    }
    __syncthreads();
    const unsigned total = offs[BMP];

    // warp-per-candidate: coalesced strided loads + deterministic tree-reduce
    for (unsigned i = wid; i < total; i += P2T / 32) {
        int r = pRow[i];
        int cand = pCand[i];
        const float* x = in + (size_t)(rowBase + r) * DDIM;
        const float* c = cb + (size_t)cand * DDIM;
        float acc = 0.f;
        #pragma unroll
        for (int k = 0; k < 16; k++)
            acc = __fmaf_rn(x[l + k * 32], c[l + k * 32], acc);
        #pragma unroll
        for (int o = 16; o; o >>= 1) acc += __shfl_xor_sync(0xFFFFFFFFu, acc, o);
        if (l == 0) {
            float s = __fsub_rn(__fadd_rn(g_rnorm[rowBase + r], g_cnorm[cand]),
                                __fmul_rn(2.0f, acc));
            unsigned long long key =
                ((unsigned long long)__float_as_uint(s) << 32) | (unsigned)cand;
            atomicMin(&best[r], key);
        }
    }
    // overflow fallback (expected never): warp-parallel full row scan
    for (int r = 0; r < BMP; r++) {
        if (cnts[r] > CAP) {
            const float* x = in + (size_t)(rowBase + r) * DDIM;
            for (int cand = wid; cand < KCODES; cand += P2T / 32) {
                const float* c = cb + (size_t)cand * DDIM;
                float acc = 0.f;
                #pragma unroll
                for (int k = 0; k < 16; k++)
                    acc = __fmaf_rn(x[l + k * 32], c[l + k * 32], acc);
                #pragma unroll
                for (int o = 16; o; o >>= 1) acc += __shfl_xor_sync(0xFFFFFFFFu, acc, o);
                if (l == 0) {
                    float s = __fsub_rn(__fadd_rn(g_rnorm[rowBase + r], g_cnorm[cand]),
                                        __fmul_rn(2.0f, acc));
                    unsigned long long key =
                        ((unsigned long long)__float_as_uint(s) << 32) | (unsigned)cand;
                    atomicMin(&best[r], key);
                }
            }
        }
    }
    __syncthreads();

    float lv = 0.f;
    if (tid < BMP) {
        unsigned long long k = best[tid];
        int bi = (int)(unsigned)(k & 0xFFFFFFFFull);
        float bs = __uint_as_float((unsigned)(k >> 32));
        idx_s[tid] = bi;
        atomicAdd(&g_hist[bi], 1u);
        lv = bs;                                // exact min lattice score = ||x-c||^2
    }
    #pragma unroll
    for (int o = 16; o; o >>= 1) lv += __shfl_down_sync(0xFFFFFFFFu, lv, o);
    if ((tid & 31) == 0) red16[wid] = lv;
    __syncthreads();
    if (tid == 0) {
        float s = 0.f;
        #pragma unroll
        for (int w = 0; w < P2T / 32; w++) s += red16[w];
        atomicAdd(&g_sumsq, (double)s);
    }
    // gather-write quantized
    for (int e = tid; e < BMP * DDIM; e += P2T) {
        int rr = e >> 9, cc = e & 511;
        out[1 + (size_t)(rowBase + rr) * DDIM + cc] = cb[(size_t)idx_s[rr] * DDIM + cc];
    }
}

// ---------------- finalize scalars ----------------
__global__ void vq_final(float* __restrict__ out, int out_size) {
    int t = threadIdx.x;                            // 1024
    float p = (float)g_hist[t] / (float)NR;
    double term = (double)(p * logf(p + 1e-10f));
    #pragma unroll
    for (int o = 16; o; o >>= 1) term += __shfl_down_sync(0xFFFFFFFFu, term, o);
    __shared__ double ws[32];
    if ((t & 31) == 0) ws[t >> 5] = term;
    __syncthreads();
    if (t == 0) {
        double s = 0.0;
        #pragma unroll
        for (int w = 0; w < 32; w++) s += ws[w];
        double mean = g_sumsq / ((double)NR * (double)DDIM);
        out[0] = (float)(1.25 * mean);
        out[out_size - 1] = (float)exp(-s);
    }
}

extern "C" void kernel_launch(void* const* d_in, const int* in_sizes, int n_in,
                              void* d_out, int out_size) {
    const float* inputs = (const float*)d_in[0];
    const float* cb     = (const float*)d_in[1];
    float* out = (float*)d_out;
    int nrows = in_sizes[0] / DDIM;

    cudaFuncSetAttribute(vq_main, cudaFuncAttributeMaxDynamicSharedMemorySize, SMEM_TOTAL);
    vq_prep_cb<<<KCODES, 128>>>(cb);
    vq_prep_rows<<<nrows / 8, 256>>>(inputs);
    vq_main<<<nrows / BM, 256, SMEM_TOTAL>>>(inputs, cb, out);
    vq_phase2<<<nrows / BMP, P2T>>>(inputs, cb, out);   // slot #4 for ncu
    vq_final<<<1, KCODES>>>(out, out_size);
}

// round 15
// speedup vs baseline: 1.1891x; 1.1763x over previous
#include <cuda_runtime.h>
#include <cuda_fp16.h>
#include <math.h>

#define DDIM 512
#define KCODES 1024
#define NR 65536
#define BM 128
#define BN 128
#define BK 32
#define NCH (DDIM/BK)        // 16
#define NSWEEP (KCODES/BN)   // 8
#define RSTR 80              // smem row stride bytes (conflict-free for ldsm)
#define CAP 32
#define MARGIN 3.0e-3f
#define BMP 32               // phase2 rows per block
#define THR 512              // vq_main threads

// dynamic smem layout (bytes)
#define OFF_CN   0
#define OFF_RMIN 4096
#define OFF_CNT  4608
#define OFF_LIST 5120
#define OFF_T    21504
#define TILEA    (BM*RSTR)           // 10240
#define TILEB    (BN*RSTR)           // 10240
#define BUF      (TILEA + TILEB)     // 20480: Ah, Bh
#define SMEM_TOTAL (OFF_T + 3*BUF)   // 82944 -> 2 CTAs/SM

__device__ float        g_cnorm[KCODES];
__device__ float        g_rnorm[NR];
__device__ unsigned int g_hist[KCODES];
__device__ double       g_sumsq;
__device__ __half       g_Ah[(size_t)NR * DDIM];
__device__ __half       g_Bh[KCODES * DDIM];
__device__ unsigned int g_candCnt[NR];
__device__ unsigned int g_cand[(size_t)NR * CAP];

// ---------------- helpers ----------------
__device__ __forceinline__ unsigned smem_u32(const void* p) {
    unsigned a;
    asm("{ .reg .u64 t; cvta.to.shared.u64 t, %1; cvt.u32.u64 %0, t; }" : "=r"(a) : "l"(p));
    return a;
}
// monotone float<->uint maps (unsigned order == float order, handles negatives)
__device__ __forceinline__ unsigned f2ord(float f) {
    unsigned b = __float_as_uint(f);
    return b ^ ((b & 0x80000000u) ? 0xFFFFFFFFu : 0x80000000u);
}
__device__ __forceinline__ float ord2f(unsigned k) {
    unsigned b = k ^ ((k & 0x80000000u) ? 0x80000000u : 0xFFFFFFFFu);
    return __uint_as_float(b);
}
__device__ __forceinline__ void ldsm4(unsigned* r, unsigned a) {
    asm volatile("ldmatrix.sync.aligned.m8n8.x4.shared.b16 {%0,%1,%2,%3}, [%4];"
        : "=r"(r[0]), "=r"(r[1]), "=r"(r[2]), "=r"(r[3]) : "r"(a));
}
__device__ __forceinline__ void mma16816(float* d, const unsigned* a, const unsigned* b) {
    asm volatile("mma.sync.aligned.m16n8k16.row.col.f32.f16.f16.f32 "
        "{%0,%1,%2,%3}, {%4,%5,%6,%7}, {%8,%9}, {%0,%1,%2,%3};"
        : "+f"(d[0]), "+f"(d[1]), "+f"(d[2]), "+f"(d[3])
        : "r"(a[0]), "r"(a[1]), "r"(a[2]), "r"(a[3]), "r"(b[0]), "r"(b[1]));
}
__device__ __forceinline__ void cpa16(unsigned dst, const void* src) {
    asm volatile("cp.async.cg.shared.global [%0], [%1], 16;" :: "r"(dst), "l"(src) : "memory");
}
#define CPA_COMMIT() asm volatile("cp.async.commit_group;" ::: "memory")
#define CPA_WAIT1()  asm volatile("cp.async.wait_group 1;" ::: "memory")
#define CPA_WAIT0()  asm volatile("cp.async.wait_group 0;" ::: "memory")

// ---------------- prep: codebook norms + f16 hi + zero accum ----------------
__global__ void vq_prep_cb(const float* __restrict__ cb) {
    int k = blockIdx.x, t = threadIdx.x;                    // 128 threads
    float4 q = ((const float4*)(cb + (size_t)k * DDIM))[t];
    double v = (double)__fmul_rn(q.x, q.x) + (double)__fmul_rn(q.y, q.y)
             + (double)__fmul_rn(q.z, q.z) + (double)__fmul_rn(q.w, q.w);
    #pragma unroll
    for (int o = 16; o; o >>= 1) v += __shfl_down_sync(0xFFFFFFFFu, v, o);
    __shared__ double ws[4];
    if ((t & 31) == 0) ws[t >> 5] = v;
    unsigned h0 = __half_as_ushort(__float2half_rn(q.x));
    unsigned h1 = __half_as_ushort(__float2half_rn(q.y));
    unsigned h2 = __half_as_ushort(__float2half_rn(q.z));
    unsigned h3 = __half_as_ushort(__float2half_rn(q.w));
    uint2 uh = {h0 | (h1 << 16), h2 | (h3 << 16)};
    ((uint2*)(g_Bh + (size_t)k * DDIM))[t] = uh;
    __syncthreads();
    if (t == 0) {
        g_cnorm[k] = (float)(ws[0] + ws[1] + ws[2] + ws[3]);
        g_hist[k] = 0u;
        if (k == 0) g_sumsq = 0.0;
    }
}

// ---------------- prep: per-row norms (f32 Kahan + f64 reduce) + A f16 hi ----------------
__global__ void vq_prep_rows(const float* __restrict__ in) {
    int wid = threadIdx.x >> 5, lid = threadIdx.x & 31;
    int row = blockIdx.x * 8 + wid;
    const float4* rp = (const float4*)(in + (size_t)row * DDIM);
    float s = 0.f, comp = 0.f;
    #pragma unroll
    for (int i = 0; i < 4; i++) {
        float4 v = rp[lid + i * 32];
        float sq[4] = {__fmul_rn(v.x, v.x), __fmul_rn(v.y, v.y),
                       __fmul_rn(v.z, v.z), __fmul_rn(v.w, v.w)};
        #pragma unroll
        for (int j = 0; j < 4; j++) {        // Kahan compensated sum (no FMA reassoc)
            float y = __fsub_rn(sq[j], comp);
            float t = __fadd_rn(s, y);
            comp = __fsub_rn(__fsub_rn(t, s), y);
            s = t;
        }
        unsigned h0 = __half_as_ushort(__float2half_rn(v.x));
        unsigned h1 = __half_as_ushort(__float2half_rn(v.y));
        unsigned h2 = __half_as_ushort(__float2half_rn(v.z));
        unsigned h3 = __half_as_ushort(__float2half_rn(v.w));
        uint2 uh = {h0 | (h1 << 16), h2 | (h3 << 16)};
        ((uint2*)(g_Ah + (size_t)row * DDIM))[lid + i * 32] = uh;
    }
    double d = (double)s - (double)comp;     // carry compensation into f64 reduce
    #pragma unroll
    for (int o = 16; o; o >>= 1) d += __shfl_down_sync(0xFFFFFFFFu, d, o);
    if (lid == 0) { g_rnorm[row] = (float)d; g_candCnt[row] = 0u; }
}

// ---------------- main: coarse f16 GEMM (512 thr, 32x32 warp tiles) ----------------
__global__ void __launch_bounds__(THR, 2)
vq_main(const float* __restrict__ in, const float* __restrict__ cb,
        float* __restrict__ out) {
    extern __shared__ char smem[];
    const unsigned sb = smem_u32(smem);
    float* cn_s = (float*)(smem + OFF_CN);
    unsigned* rowMinU = (unsigned*)(smem + OFF_RMIN);
    unsigned* cnt_s   = (unsigned*)(smem + OFF_CNT);
    unsigned* list_s  = (unsigned*)(smem + OFF_LIST);
    const int tid = threadIdx.x, l = tid & 31, wid = tid >> 5;
    const int wm = wid >> 2, wn = wid & 3;            // 4m x 4n warp grid, 32x32 tiles
    const int rowBase = blockIdx.x * BM;

    for (int i = tid; i < KCODES; i += THR) cn_s[i] = g_cnorm[i];
    if (tid < BM) { rowMinU[tid] = 0xFFFFFFFFu; cnt_s[tid] = 0u; }

    const unsigned aRB  = (l & 15) * RSTR + (l >> 4) * 16;
    const unsigned bRB4 = ((l >> 4) * 8 + (l & 7)) * RSTR + ((l >> 3) & 1) * 16;
    // staging: row = tid>>2 (4 threads/row), 16B quarter = tid&3
    const int sRow = tid >> 2, sQ = tid & 3;
    const unsigned sDst = sRow * RSTR + sQ * 16;

    int rloc[4];
    #pragma unroll
    for (int s = 0; s < 4; s++)
        rloc[s] = wm * 32 + (s >> 1) * 16 + (s & 1) * 8 + (l >> 2);

    __syncthreads();

    for (int sw = 0; sw < NSWEEP; sw++) {
        const int kc0 = sw * BN;
        float D0[2][4][4];
        #pragma unroll
        for (int mt = 0; mt < 2; mt++)
            #pragma unroll
            for (int nt = 0; nt < 4; nt++)
                #pragma unroll
                for (int e = 0; e < 4; e++) D0[mt][nt][e] = 0.f;

        auto stage = [&](int c, int b) {
            const __half* pa = g_Ah + (size_t)(rowBase + sRow) * DDIM + c * BK + sQ * 8;
            const __half* pb = g_Bh + (size_t)(kc0 + sRow) * DDIM + c * BK + sQ * 8;
            const unsigned base = sb + OFF_T + b * BUF;
            cpa16(base + sDst,         pa);
            cpa16(base + TILEA + sDst, pb);
            CPA_COMMIT();
        };
        __syncthreads();                        // prior readers of buf0/1 done
        stage(0, 0);
        stage(1, 1);

        for (int c = 0; c < NCH; c++) {
            if (c == NCH - 1) { CPA_WAIT0(); } else { CPA_WAIT1(); }
            __syncthreads();                    // chunk c visible; compute(c-1) done
            if (c + 2 < NCH) stage(c + 2, (c + 2) % 3);
            const unsigned base = sb + OFF_T + (c % 3) * BUF;
            #pragma unroll
            for (int kk = 0; kk < 2; kk++) {
                const unsigned ko = kk * 32;
                unsigned ah[2][4], bh[4][2];
                #pragma unroll
                for (int mt = 0; mt < 2; mt++)
                    ldsm4(ah[mt], base + (wm * 32 + mt * 16) * RSTR + aRB + ko);
                #pragma unroll
                for (int p = 0; p < 2; p++) {
                    unsigned t4[4];
                    ldsm4(t4, base + TILEA + (wn * 32 + p * 16) * RSTR + bRB4 + ko);
                    bh[2*p][0] = t4[0]; bh[2*p][1] = t4[1];
                    bh[2*p+1][0] = t4[2]; bh[2*p+1][1] = t4[3];
                }
                #pragma unroll
                for (int mt = 0; mt < 2; mt++)
                    #pragma unroll
                    for (int nt = 0; nt < 4; nt++)
                        mma16816(D0[mt][nt], ah[mt], bh[nt]);
            }
        }

        // pass A: compute coarse scores in-place + running per-row min
        float sMin[4];
        #pragma unroll
        for (int s = 0; s < 4; s++) sMin[s] = 3.4e38f;
        #pragma unroll
        for (int mt = 0; mt < 2; mt++)
            #pragma unroll
            for (int nt = 0; nt < 4; nt++)
                #pragma unroll
                for (int e = 0; e < 4; e++) {
                    int col = kc0 + wn * 32 + nt * 8 + (l & 3) * 2 + (e & 1);
                    float s = __fsub_rn(cn_s[col], __fadd_rn(D0[mt][nt][e], D0[mt][nt][e]));
                    D0[mt][nt][e] = s;          // reuse in pass B
                    int slot = mt * 2 + (e >> 1);
                    if (s < sMin[slot]) sMin[slot] = s;
                }
        #pragma unroll
        for (int s = 0; s < 4; s++) {
            sMin[s] = fminf(sMin[s], __shfl_xor_sync(0xFFFFFFFFu, sMin[s], 1));
            sMin[s] = fminf(sMin[s], __shfl_xor_sync(0xFFFFFFFFu, sMin[s], 2));
        }
        if ((l & 3) == 0) {
            #pragma unroll
            for (int s = 0; s < 4; s++)
                atomicMin(&rowMinU[rloc[s]], f2ord(sMin[s]));
        }
        __syncthreads();
        // pass B: collect candidates within MARGIN of running row min
        float th[4];
        #pragma unroll
        for (int s = 0; s < 4; s++)
            th[s] = __fadd_rn(ord2f(rowMinU[rloc[s]]), MARGIN);
        #pragma unroll
        for (int mt = 0; mt < 2; mt++)
            #pragma unroll
            for (int nt = 0; nt < 4; nt++)
                #pragma unroll
                for (int e = 0; e < 4; e++) {
                    int slot = mt * 2 + (e >> 1);
                    if (D0[mt][nt][e] < th[slot]) {
                        int col = kc0 + wn * 32 + nt * 8 + (l & 3) * 2 + (e & 1);
                        unsigned pos = atomicAdd(&cnt_s[rloc[slot]], 1u);
                        if (pos < CAP) list_s[rloc[slot] * CAP + pos] = (unsigned)col;
                    }
                }
    }

    __syncthreads();
    if (tid < BM) g_candCnt[rowBase + tid] = cnt_s[tid];
    for (int i = tid; i < BM * CAP; i += THR) {
        int r = i / CAP, j = i % CAP;
        g_cand[(size_t)(rowBase + r) * CAP + j] = list_s[r * CAP + j];
    }
}

// ---------------- phase 2: exact rescoring (32 rows/block) + outputs ----------------
__global__ void __launch_bounds__(256)
vq_phase2(const float* __restrict__ in, const float* __restrict__ cb,
          float* __restrict__ out) {
    __shared__ unsigned cnts[BMP];
    __shared__ unsigned offs[BMP + 1];
    __shared__ unsigned char  pRow[BMP * CAP];
    __shared__ unsigned short pCand[BMP * CAP];
    __shared__ unsigned long long best[BMP];
    __shared__ int idx_s[BMP];
    __shared__ float red8[8];
    const int tid = threadIdx.x, l = tid & 31, wid = tid >> 5;
    const int rowBase = blockIdx.x * BMP;

    if (tid < BMP) {
        best[tid] = ~0ull;
        cnts[tid] = g_candCnt[rowBase + tid];
    }
    __syncthreads();
    if (tid == 0) {
        unsigned acc = 0;
        for (int r = 0; r < BMP; r++) {
            offs[r] = acc;
            unsigned c = cnts[r];
            acc += (c <= CAP) ? c : 0u;
        }
        offs[BMP] = acc;
    }
    __syncthreads();
    if (tid < BMP && cnts[tid] <= CAP) {
        unsigned o = offs[tid];
        for (unsigned j = 0; j < cnts[tid]; j++) {
            pRow[o + j] = (unsigned char)tid;
            pCand[o + j] = (unsigned short)g_cand[(size_t)(rowBase + tid) * CAP + j];
        }
    }
    __syncthreads();
    const unsigned total = offs[BMP];

    // warp-per-candidate: coalesced strided loads + deterministic tree-reduce
    for (unsigned i = wid; i < total; i += 8) {
        int r = pRow[i];
        int cand = pCand[i];
        const float* x = in + (size_t)(rowBase + r) * DDIM;
        const float* c = cb + (size_t)cand * DDIM;
        float acc = 0.f;
        #pragma unroll
        for (int k = 0; k < 16; k++)
            acc = __fmaf_rn(x[l + k * 32], c[l + k * 32], acc);
        #pragma unroll
        for (int o = 16; o; o >>= 1) acc += __shfl_xor_sync(0xFFFFFFFFu, acc, o);
        if (l == 0) {
            float s = __fsub_rn(__fadd_rn(g_rnorm[rowBase + r], g_cnorm[cand]),
                                __fmul_rn(2.0f, acc));
            unsigned long long key =
                ((unsigned long long)__float_as_uint(s) << 32) | (unsigned)cand;
            atomicMin(&best[r], key);
        }
    }
    // overflow fallback (expected never): warp-parallel full row scan
    for (int r = 0; r < BMP; r++) {
        if (cnts[r] > CAP) {
            const float* x = in + (size_t)(rowBase + r) * DDIM;
            for (int cand = wid; cand < KCODES; cand += 8) {
                const float* c = cb + (size_t)cand * DDIM;
                float acc = 0.f;
                #pragma unroll
                for (int k = 0; k < 16; k++)
                    acc = __fmaf_rn(x[l + k * 32], c[l + k * 32], acc);
                #pragma unroll
                for (int o = 16; o; o >>= 1) acc += __shfl_xor_sync(0xFFFFFFFFu, acc, o);
                if (l == 0) {
                    float s = __fsub_rn(__fadd_rn(g_rnorm[rowBase + r], g_cnorm[cand]),
                                        __fmul_rn(2.0f, acc));
                    unsigned long long key =
                        ((unsigned long long)__float_as_uint(s) << 32) | (unsigned)cand;
                    atomicMin(&best[r], key);
                }
            }
        }
    }
    __syncthreads();

    float lv = 0.f;
    if (tid < BMP) {
        unsigned long long k = best[tid];
        int bi = (int)(unsigned)(k & 0xFFFFFFFFull);
        float bs = __uint_as_float((unsigned)(k >> 32));
        idx_s[tid] = bi;
        atomicAdd(&g_hist[bi], 1u);
        lv = bs;                                // exact min lattice score = ||x-c||^2
    }
    #pragma unroll
    for (int o = 16; o; o >>= 1) lv += __shfl_down_sync(0xFFFFFFFFu, lv, o);
    if ((tid & 31) == 0) red8[wid] = lv;
    __syncthreads();
    if (tid == 0) {
        float s = 0.f;
        #pragma unroll
        for (int w = 0; w < 8; w++) s += red8[w];
        atomicAdd(&g_sumsq, (double)s);
    }
    // gather-write quantized
    for (int e = tid; e < BMP * DDIM; e += 256) {
        int rr = e >> 9, cc = e & 511;
        out[1 + (size_t)(rowBase + rr) * DDIM + cc] = cb[(size_t)idx_s[rr] * DDIM + cc];
    }
}

// ---------------- finalize scalars ----------------
__global__ void vq_final(float* __restrict__ out, int out_size) {
    int t = threadIdx.x;                            // 1024
    float p = (float)g_hist[t] / (float)NR;
    double term = (double)(p * logf(p + 1e-10f));
    #pragma unroll
    for (int o = 16; o; o >>= 1) term += __shfl_down_sync(0xFFFFFFFFu, term, o);
    __shared__ double ws[32];
    if ((t & 31) == 0) ws[t >> 5] = term;
    __syncthreads();
    if (t == 0) {
        double s = 0.0;
        #pragma unroll
        for (int w = 0; w < 32; w++) s += ws[w];
        double mean = g_sumsq / ((double)NR * (double)DDIM);
        out[0] = (float)(1.25 * mean);
        out[out_size - 1] = (float)exp(-s);
    }
}

extern "C" void kernel_launch(void* const* d_in, const int* in_sizes, int n_in,
                              void* d_out, int out_size) {
    const float* inputs = (const float*)d_in[0];
    const float* cb     = (const float*)d_in[1];
    float* out = (float*)d_out;
    int nrows = in_sizes[0] / DDIM;

    cudaFuncSetAttribute(vq_main, cudaFuncAttributeMaxDynamicSharedMemorySize, SMEM_TOTAL);
    vq_prep_cb<<<KCODES, 128>>>(cb);
    vq_prep_rows<<<nrows / 8, 256>>>(inputs);
    vq_main<<<nrows / BM, THR, SMEM_TOTAL>>>(inputs, cb, out);
    vq_phase2<<<nrows / BMP, 256>>>(inputs, cb, out);   // slot #4 for ncu
    vq_final<<<1, KCODES>>>(out, out_size);
}

// round 17
// speedup vs baseline: 1.2487x; 1.0502x over previous
#include <cuda_runtime.h>
#include <cuda_fp16.h>
#include <math.h>

#define DDIM 512
#define KCODES 1024
#define NR 65536
#define BM 128
#define BN 128
#define BK 32
#define NCH (DDIM/BK)        // 16
#define NSWEEP (KCODES/BN)   // 8
#define RSTR 80              // smem row stride bytes (conflict-free for ldsm)
#define CAP 32
#define MARGIN 3.0e-3f
#define THR 512              // vq_main threads

// dynamic smem layout (bytes)
#define OFF_CN   0
#define OFF_RMIN 4096
#define OFF_CNT  4608
#define OFF_LIST 5120
#define OFF_T    21504
#define TILEA    (BM*RSTR)           // 10240
#define TILEB    (BN*RSTR)           // 10240
#define BUF      (TILEA + TILEB)     // 20480: Ah, Bh
#define SMEM_TOTAL (OFF_T + 3*BUF)   // 82944 -> 2 CTAs/SM

__device__ float        g_cnorm[KCODES];
__device__ float        g_rnorm[NR];
__device__ unsigned int g_hist[KCODES];
__device__ double       g_sumsqA[64];
__device__ __half       g_Ah[(size_t)NR * DDIM];
__device__ __half       g_Bh[KCODES * DDIM];
__device__ unsigned int g_candCnt[NR];
__device__ unsigned int g_cand[(size_t)NR * CAP];

// ---------------- helpers ----------------
__device__ __forceinline__ unsigned smem_u32(const void* p) {
    unsigned a;
    asm("{ .reg .u64 t; cvta.to.shared.u64 t, %1; cvt.u32.u64 %0, t; }" : "=r"(a) : "l"(p));
    return a;
}
// monotone float<->uint maps (unsigned order == float order, handles negatives)
__device__ __forceinline__ unsigned f2ord(float f) {
    unsigned b = __float_as_uint(f);
    return b ^ ((b & 0x80000000u) ? 0xFFFFFFFFu : 0x80000000u);
}
__device__ __forceinline__ float ord2f(unsigned k) {
    unsigned b = k ^ ((k & 0x80000000u) ? 0x80000000u : 0xFFFFFFFFu);
    return __uint_as_float(b);
}
__device__ __forceinline__ void ldsm4(unsigned* r, unsigned a) {
    asm volatile("ldmatrix.sync.aligned.m8n8.x4.shared.b16 {%0,%1,%2,%3}, [%4];"
        : "=r"(r[0]), "=r"(r[1]), "=r"(r[2]), "=r"(r[3]) : "r"(a));
}
__device__ __forceinline__ void mma16816(float* d, const unsigned* a, const unsigned* b) {
    asm volatile("mma.sync.aligned.m16n8k16.row.col.f32.f16.f16.f32 "
        "{%0,%1,%2,%3}, {%4,%5,%6,%7}, {%8,%9}, {%0,%1,%2,%3};"
        : "+f"(d[0]), "+f"(d[1]), "+f"(d[2]), "+f"(d[3])
        : "r"(a[0]), "r"(a[1]), "r"(a[2]), "r"(a[3]), "r"(b[0]), "r"(b[1]));
}
__device__ __forceinline__ void cpa16(unsigned dst, const void* src) {
    asm volatile("cp.async.cg.shared.global [%0], [%1], 16;" :: "r"(dst), "l"(src) : "memory");
}
#define CPA_COMMIT() asm volatile("cp.async.commit_group;" ::: "memory")
#define CPA_WAIT1()  asm volatile("cp.async.wait_group 1;" ::: "memory")
#define CPA_WAIT0()  asm volatile("cp.async.wait_group 0;" ::: "memory")

// ---------------- prep: codebook norms + f16 hi + zero accum ----------------
__global__ void vq_prep_cb(const float* __restrict__ cb) {
    int k = blockIdx.x, t = threadIdx.x;                    // 128 threads
    float4 q = ((const float4*)(cb + (size_t)k * DDIM))[t];
    double v = (double)__fmul_rn(q.x, q.x) + (double)__fmul_rn(q.y, q.y)
             + (double)__fmul_rn(q.z, q.z) + (double)__fmul_rn(q.w, q.w);
    #pragma unroll
    for (int o = 16; o; o >>= 1) v += __shfl_down_sync(0xFFFFFFFFu, v, o);
    __shared__ double ws[4];
    if ((t & 31) == 0) ws[t >> 5] = v;
    unsigned h0 = __half_as_ushort(__float2half_rn(q.x));
    unsigned h1 = __half_as_ushort(__float2half_rn(q.y));
    unsigned h2 = __half_as_ushort(__float2half_rn(q.z));
    unsigned h3 = __half_as_ushort(__float2half_rn(q.w));
    uint2 uh = {h0 | (h1 << 16), h2 | (h3 << 16)};
    ((uint2*)(g_Bh + (size_t)k * DDIM))[t] = uh;
    __syncthreads();
    if (t == 0) {
        g_cnorm[k] = (float)(ws[0] + ws[1] + ws[2] + ws[3]);
        g_hist[k] = 0u;
        if (k < 64) g_sumsqA[k] = 0.0;
    }
}

// ---------------- prep: per-row norms (f32 Kahan + f64 reduce) + A f16 hi ----------------
__global__ void vq_prep_rows(const float* __restrict__ in) {
    int wid = threadIdx.x >> 5, lid = threadIdx.x & 31;
    int row = blockIdx.x * 8 + wid;
    const float4* rp = (const float4*)(in + (size_t)row * DDIM);
    float s = 0.f, comp = 0.f;
    #pragma unroll
    for (int i = 0; i < 4; i++) {
        float4 v = rp[lid + i * 32];
        float sq[4] = {__fmul_rn(v.x, v.x), __fmul_rn(v.y, v.y),
                       __fmul_rn(v.z, v.z), __fmul_rn(v.w, v.w)};
        #pragma unroll
        for (int j = 0; j < 4; j++) {        // Kahan compensated sum (no FMA reassoc)
            float y = __fsub_rn(sq[j], comp);
            float t = __fadd_rn(s, y);
            comp = __fsub_rn(__fsub_rn(t, s), y);
            s = t;
        }
        unsigned h0 = __half_as_ushort(__float2half_rn(v.x));
        unsigned h1 = __half_as_ushort(__float2half_rn(v.y));
        unsigned h2 = __half_as_ushort(__float2half_rn(v.z));
        unsigned h3 = __half_as_ushort(__float2half_rn(v.w));
        uint2 uh = {h0 | (h1 << 16), h2 | (h3 << 16)};
        ((uint2*)(g_Ah + (size_t)row * DDIM))[lid + i * 32] = uh;
    }
    double d = (double)s - (double)comp;     // carry compensation into f64 reduce
    #pragma unroll
    for (int o = 16; o; o >>= 1) d += __shfl_down_sync(0xFFFFFFFFu, d, o);
    if (lid == 0) { g_rnorm[row] = (float)d; g_candCnt[row] = 0u; }
}

// ---------------- main: coarse f16 GEMM (512 thr, 32x32 warp tiles) ----------------
__global__ void __launch_bounds__(THR, 2)
vq_main(const float* __restrict__ in, const float* __restrict__ cb,
        float* __restrict__ out) {
    extern __shared__ char smem[];
    const unsigned sb = smem_u32(smem);
    float* cn_s = (float*)(smem + OFF_CN);
    unsigned* rowMinU = (unsigned*)(smem + OFF_RMIN);
    unsigned* cnt_s   = (unsigned*)(smem + OFF_CNT);
    unsigned* list_s  = (unsigned*)(smem + OFF_LIST);
    const int tid = threadIdx.x, l = tid & 31, wid = tid >> 5;
    const int wm = wid >> 2, wn = wid & 3;            // 4m x 4n warp grid, 32x32 tiles
    const int rowBase = blockIdx.x * BM;

    for (int i = tid; i < KCODES; i += THR) cn_s[i] = g_cnorm[i];
    if (tid < BM) { rowMinU[tid] = 0xFFFFFFFFu; cnt_s[tid] = 0u; }

    const unsigned aRB  = (l & 15) * RSTR + (l >> 4) * 16;
    const unsigned bRB4 = ((l >> 4) * 8 + (l & 7)) * RSTR + ((l >> 3) & 1) * 16;
    // staging: row = tid>>2 (4 threads/row), 16B quarter = tid&3
    const int sRow = tid >> 2, sQ = tid & 3;
    const unsigned sDst = sRow * RSTR + sQ * 16;

    int rloc[4];
    #pragma unroll
    for (int s = 0; s < 4; s++)
        rloc[s] = wm * 32 + (s >> 1) * 16 + (s & 1) * 8 + (l >> 2);

    __syncthreads();

    for (int sw = 0; sw < NSWEEP; sw++) {
        const int kc0 = sw * BN;
        float D0[2][4][4];
        #pragma unroll
        for (int mt = 0; mt < 2; mt++)
            #pragma unroll
            for (int nt = 0; nt < 4; nt++)
                #pragma unroll
                for (int e = 0; e < 4; e++) D0[mt][nt][e] = 0.f;

        auto stage = [&](int c, int b) {
            const __half* pa = g_Ah + (size_t)(rowBase + sRow) * DDIM + c * BK + sQ * 8;
            const __half* pb = g_Bh + (size_t)(kc0 + sRow) * DDIM + c * BK + sQ * 8;
            const unsigned base = sb + OFF_T + b * BUF;
            cpa16(base + sDst,         pa);
            cpa16(base + TILEA + sDst, pb);
            CPA_COMMIT();
        };
        __syncthreads();                        // prior readers of buf0/1 done
        stage(0, 0);
        stage(1, 1);

        for (int c = 0; c < NCH; c++) {
            if (c == NCH - 1) { CPA_WAIT0(); } else { CPA_WAIT1(); }
            __syncthreads();                    // chunk c visible; compute(c-1) done
            if (c + 2 < NCH) stage(c + 2, (c + 2) % 3);
            const unsigned base = sb + OFF_T + (c % 3) * BUF;
            #pragma unroll
            for (int kk = 0; kk < 2; kk++) {
                const unsigned ko = kk * 32;
                unsigned ah[2][4], bh[4][2];
                #pragma unroll
                for (int mt = 0; mt < 2; mt++)
                    ldsm4(ah[mt], base + (wm * 32 + mt * 16) * RSTR + aRB + ko);
                #pragma unroll
                for (int p = 0; p < 2; p++) {
                    unsigned t4[4];
                    ldsm4(t4, base + TILEA + (wn * 32 + p * 16) * RSTR + bRB4 + ko);
                    bh[2*p][0] = t4[0]; bh[2*p][1] = t4[1];
                    bh[2*p+1][0] = t4[2]; bh[2*p+1][1] = t4[3];
                }
                #pragma unroll
                for (int mt = 0; mt < 2; mt++)
                    #pragma unroll
                    for (int nt = 0; nt < 4; nt++)
                        mma16816(D0[mt][nt], ah[mt], bh[nt]);
            }
        }

        // pass A: compute coarse scores in-place + running per-row min
        float sMin[4];
        #pragma unroll
        for (int s = 0; s < 4; s++) sMin[s] = 3.4e38f;
        #pragma unroll
        for (int mt = 0; mt < 2; mt++)
            #pragma unroll
            for (int nt = 0; nt < 4; nt++)
                #pragma unroll
                for (int e = 0; e < 4; e++) {
                    int col = kc0 + wn * 32 + nt * 8 + (l & 3) * 2 + (e & 1);
                    float s = __fsub_rn(cn_s[col], __fadd_rn(D0[mt][nt][e], D0[mt][nt][e]));
                    D0[mt][nt][e] = s;          // reuse in pass B
                    int slot = mt * 2 + (e >> 1);
                    if (s < sMin[slot]) sMin[slot] = s;
                }
        #pragma unroll
        for (int s = 0; s < 4; s++) {
            sMin[s] = fminf(sMin[s], __shfl_xor_sync(0xFFFFFFFFu, sMin[s], 1));
            sMin[s] = fminf(sMin[s], __shfl_xor_sync(0xFFFFFFFFu, sMin[s], 2));
        }
        if ((l & 3) == 0) {
            #pragma unroll
            for (int s = 0; s < 4; s++)
                atomicMin(&rowMinU[rloc[s]], f2ord(sMin[s]));
        }
        __syncthreads();
        // pass B: collect candidates within MARGIN of running row min
        float th[4];
        #pragma unroll
        for (int s = 0; s < 4; s++)
            th[s] = __fadd_rn(ord2f(rowMinU[rloc[s]]), MARGIN);
        #pragma unroll
        for (int mt = 0; mt < 2; mt++)
            #pragma unroll
            for (int nt = 0; nt < 4; nt++)
                #pragma unroll
                for (int e = 0; e < 4; e++) {
                    int slot = mt * 2 + (e >> 1);
                    if (D0[mt][nt][e] < th[slot]) {
                        int col = kc0 + wn * 32 + nt * 8 + (l & 3) * 2 + (e & 1);
                        unsigned pos = atomicAdd(&cnt_s[rloc[slot]], 1u);
                        if (pos < CAP) list_s[rloc[slot] * CAP + pos] = (unsigned)col;
                    }
                }
    }

    __syncthreads();
    if (tid < BM) g_candCnt[rowBase + tid] = cnt_s[tid];
    for (int i = tid; i < BM * CAP; i += THR) {
        int r = i / CAP, j = i % CAP;
        g_cand[(size_t)(rowBase + r) * CAP + j] = list_s[r * CAP + j];
    }
}

// ---------------- phase 2: exact rescoring, warp-per-row + outputs ----------------
__global__ void __launch_bounds__(256)
vq_phase2(const float* __restrict__ in, const float* __restrict__ cb,
          float* __restrict__ out) {
    __shared__ float redS[8];
    const int tid = threadIdx.x, l = tid & 31, wid = tid >> 5;
    const int row = blockIdx.x * 8 + wid;

    const unsigned cnt = g_candCnt[row];
    const float* x = in + (size_t)row * DDIM;
    const float rs = g_rnorm[row];
    unsigned long long bestKey = ~0ull;       // tracked in all lanes (key from lane0 bcast)

    if (cnt <= CAP) {
        for (unsigned j = 0; j < cnt; j++) {
            int cand = (int)g_cand[(size_t)row * CAP + j];   // uniform -> broadcast
            const float* c = cb + (size_t)cand * DDIM;
            float acc = 0.f;
            #pragma unroll
            for (int k = 0; k < 16; k++)
                acc = __fmaf_rn(x[l + k * 32], c[l + k * 32], acc);
            #pragma unroll
            for (int o = 16; o; o >>= 1) acc += __shfl_xor_sync(0xFFFFFFFFu, acc, o);
            float s = __fsub_rn(__fadd_rn(rs, g_cnorm[cand]), __fmul_rn(2.0f, acc));
            unsigned long long key =
                ((unsigned long long)__float_as_uint(s) << 32) | (unsigned)cand;
            if (key < bestKey) bestKey = key;
        }
    } else {
        // overflow fallback (expected never): full row scan by this warp
        for (int cand = 0; cand < KCODES; cand++) {
            const float* c = cb + (size_t)cand * DDIM;
            float acc = 0.f;
            #pragma unroll
            for (int k = 0; k < 16; k++)
                acc = __fmaf_rn(x[l + k * 32], c[l + k * 32], acc);
            #pragma unroll
            for (int o = 16; o; o >>= 1) acc += __shfl_xor_sync(0xFFFFFFFFu, acc, o);
            float s = __fsub_rn(__fadd_rn(rs, g_cnorm[cand]), __fmul_rn(2.0f, acc));
            unsigned long long key =
                ((unsigned long long)__float_as_uint(s) << 32) | (unsigned)cand;
            if (key < bestKey) bestKey = key;
        }
    }

    const int   bi = (int)(unsigned)(bestKey & 0xFFFFFFFFull);
    const float bs = __uint_as_float((unsigned)(bestKey >> 32));
    if (l == 0) {
        atomicAdd(&g_hist[bi], 1u);
        redS[wid] = bs;                          // exact min score = ||x-c||^2
    }
    __syncthreads();
    if (tid == 0) {
        float s = 0.f;
        #pragma unroll
        for (int w = 0; w < 8; w++) s += redS[w];
        atomicAdd(&g_sumsqA[blockIdx.x & 63], (double)s);
    }
    // gather-write quantized (warp-per-row, coalesced 128B segments)
    {
        const float* c = cb + (size_t)bi * DDIM;
        float* o = out + 1 + (size_t)row * DDIM;
        #pragma unroll
        for (int k = 0; k < 16; k++)
            o[l + k * 32] = c[l + k * 32];
    }
}

// ---------------- finalize scalars ----------------
__global__ void vq_final(float* __restrict__ out, int out_size) {
    int t = threadIdx.x;                            // 1024
    float p = (float)g_hist[t] / (float)NR;
    double term = (double)(p * logf(p + 1e-10f));
    #pragma unroll
    for (int o = 16; o; o >>= 1) term += __shfl_down_sync(0xFFFFFFFFu, term, o);
    __shared__ double ws[32];
    if ((t & 31) == 0) ws[t >> 5] = term;
    __syncthreads();
    if (t == 0) {
        double s = 0.0;
        #pragma unroll
        for (int w = 0; w < 32; w++) s += ws[w];
        double qs = 0.0;
        #pragma unroll
        for (int w = 0; w < 64; w++) qs += g_sumsqA[w];
        double mean = qs / ((double)NR * (double)DDIM);
        out[0] = (float)(1.25 * mean);
        out[out_size - 1] = (float)exp(-s);
    }
}

extern "C" void kernel_launch(void* const* d_in, const int* in_sizes, int n_in,
                              void* d_out, int out_size) {
    const float* inputs = (const float*)d_in[0];
    const float* cb     = (const float*)d_in[1];
    float* out = (float*)d_out;
    int nrows = in_sizes[0] / DDIM;

    cudaFuncSetAttribute(vq_main, cudaFuncAttributeMaxDynamicSharedMemorySize, SMEM_TOTAL);
    vq_prep_cb<<<KCODES, 128>>>(cb);
    vq_prep_rows<<<nrows / 8, 256>>>(inputs);
    vq_main<<<nrows / BM, THR, SMEM_TOTAL>>>(inputs, cb, out);
    vq_phase2<<<nrows / 8, 256>>>(inputs, cb, out);   // slot #4 for ncu
    vq_final<<<1, KCODES>>>(out, out_size);
}